// round 3
// baseline (speedup 1.0000x reference)
#include <cuda_runtime.h>
#include <cstdint>

// Problem dims (fixed)
#define BB   16
#define HH   64
#define WWD  64
#define TT   4096
#define CC   256
#define NCH  32          // chunks per scan
#define CLEN 128         // T / NCH
#define NELEM (BB*TT*CC) // 16777216
#define NAGG  (BB*NCH*CC)

// ---------------- scratch (device globals; no allocation allowed) ------------
__device__ float g_xs[NELEM];
__device__ float g_k [NELEM];
__device__ float g_v [NELEM];
__device__ float g_sr[NELEM];
// per-t local backward scan states (indexed by sequence position s)
__device__ float g_bA[NELEM];
__device__ float g_bB[NELEM];
__device__ float g_bP[NELEM];
// chunk aggregates / prefixes / suffixes
__device__ float g_fA[NAGG], g_fB[NAGG], g_fP[NAGG];     // fwd chunk aggregates
__device__ float g_bAg[NAGG], g_bBg[NAGG], g_bPg[NAGG];  // bwd chunk aggregates
__device__ float g_pA[NAGG], g_pB[NAGG], g_pP[NAGG];     // fwd chunk prefixes (carry at chunk start)
__device__ float g_sA[NAGG], g_sB[NAGG], g_sP[NAGG];     // bwd chunk suffixes (anchored at chunk end)

// sequence-position -> memory-row map. JM=0: row-major (t=s). JM=1: column-major
// (s = w*H + h  ->  t = h*W + w)
template<int JM>
__device__ __forceinline__ int seqmap(int s) {
    return (JM == 0) ? s : (((s & 63) << 6) | (s >> 6));
}

// ---------------- omni_shift: fused 5x5 depthwise stencil --------------------
__global__ __launch_bounds__(256) void omni_kernel(
    const float* __restrict__ x, const float* __restrict__ alpha,
    const float* __restrict__ w1, const float* __restrict__ w3,
    const float* __restrict__ w5)
{
    int c = threadIdx.x;            // 0..255
    int b = blockIdx.x >> 6;        // grid = BB*WWD
    int w = blockIdx.x & 63;

    float a0 = alpha[0], a1 = alpha[1], a2 = alpha[2], a3 = alpha[3];

    float coef[5][5];
    #pragma unroll
    for (int r = 0; r < 5; r++)
        #pragma unroll
        for (int d = 0; d < 5; d++)
            coef[r][d] = a3 * w5[c * 25 + r * 5 + d];
    #pragma unroll
    for (int r = 0; r < 3; r++)
        #pragma unroll
        for (int d = 0; d < 3; d++)
            coef[r + 1][d + 1] += a2 * w3[c * 9 + r * 3 + d];
    coef[2][2] += a0 + a1 * w1[c];

    const float* xb = x + (size_t)b * TT * CC + c;
    float* ob = g_xs + (size_t)b * TT * CC + c;

    float win[5][5];
    // prime rows h-2 .. h+2 for h = 0
    #pragma unroll
    for (int r = 0; r < 5; r++) {
        int hr = r - 2;
        #pragma unroll
        for (int d = 0; d < 5; d++) {
            int wx = w + d - 2;
            win[r][d] = (hr >= 0 && wx >= 0 && wx < WWD) ? xb[(hr * WWD + wx) * CC] : 0.0f;
        }
    }

    for (int h = 0; h < HH; h++) {
        float acc = 0.0f;
        #pragma unroll
        for (int r = 0; r < 5; r++)
            #pragma unroll
            for (int d = 0; d < 5; d++)
                acc = fmaf(coef[r][d], win[r][d], acc);
        ob[(h * WWD + w) * CC] = acc;
        // shift window up, load row h+3
        #pragma unroll
        for (int r = 0; r < 4; r++)
            #pragma unroll
            for (int d = 0; d < 5; d++)
                win[r][d] = win[r + 1][d];
        int hr = h + 3;
        #pragma unroll
        for (int d = 0; d < 5; d++) {
            int wx = w + d - 2;
            win[4][d] = (hr < HH && wx >= 0 && wx < WWD) ? xb[(hr * WWD + wx) * CC] : 0.0f;
        }
    }
}

// ---------------- fp32 SGEMM, 128x128x16 tiles, 8x8 microtiles ---------------
// MODE 0: A = g_xs [M,256]; bx 0..5 -> {Wk|Wv|Wr} columns, writes g_k/g_v/g_sr
//         (sigmoid on the Wr part).
// MODE 1: A = g_sr * g_v elementwise; B = Wo; writes outp.
template<int MODE>
__global__ __launch_bounds__(256) void gemm_kernel(
    const float* __restrict__ W0, const float* __restrict__ W1,
    const float* __restrict__ W2, float* __restrict__ outp)
{
    __shared__ float As[16][132];   // [k][m], padded
    __shared__ float Bs[16][128];   // [k][n]

    int tid = threadIdx.x;
    int bx = blockIdx.x;
    int by = blockIdx.y;

    const float* Bsrc;
    float* Dst;
    int ncol0;
    bool sig = false;
    if (MODE == 0) {
        Bsrc  = (bx < 2) ? W0 : (bx < 4) ? W1 : W2;
        Dst   = (bx < 2) ? g_k : (bx < 4) ? g_v : g_sr;
        sig   = (bx >= 4);
        ncol0 = (bx & 1) * 128;
    } else {
        Bsrc  = W0;
        Dst   = outp;
        ncol0 = bx * 128;
    }

    int m0 = by * 128;
    int tx = tid & 15, ty = tid >> 4;

    float acc[8][8];
    #pragma unroll
    for (int i = 0; i < 8; i++)
        #pragma unroll
        for (int j = 0; j < 8; j++)
            acc[i][j] = 0.0f;

    for (int kb = 0; kb < 16; ++kb) {
        int k0 = kb * 16;
        float4 afr[2], bfr[2];
        #pragma unroll
        for (int q = 0; q < 2; q++) {
            int id = tid + q * 256;
            int ar = id >> 2, ac = (id & 3) * 4;
            int aidx = (m0 + ar) * CC + k0 + ac;
            if (MODE == 0) {
                afr[q] = *(const float4*)&g_xs[aidx];
            } else {
                float4 s4 = *(const float4*)&g_sr[aidx];
                float4 v4 = *(const float4*)&g_v[aidx];
                afr[q] = make_float4(s4.x * v4.x, s4.y * v4.y, s4.z * v4.z, s4.w * v4.w);
            }
            int br = id >> 5, bc = (id & 31) * 4;
            bfr[q] = *(const float4*)&Bsrc[(k0 + br) * CC + ncol0 + bc];
        }
        __syncthreads();   // previous iteration's compute done
        #pragma unroll
        for (int q = 0; q < 2; q++) {
            int id = tid + q * 256;
            int ar = id >> 2, ac = (id & 3) * 4;
            As[ac + 0][ar] = afr[q].x;
            As[ac + 1][ar] = afr[q].y;
            As[ac + 2][ar] = afr[q].z;
            As[ac + 3][ar] = afr[q].w;
            int br = id >> 5, bc = (id & 31) * 4;
            *(float4*)&Bs[br][bc] = bfr[q];
        }
        __syncthreads();
        #pragma unroll
        for (int kk = 0; kk < 16; kk++) {
            float ra[8], rb[8];
            *(float4*)&ra[0] = *(const float4*)&As[kk][ty * 8];
            *(float4*)&ra[4] = *(const float4*)&As[kk][ty * 8 + 4];
            *(float4*)&rb[0] = *(const float4*)&Bs[kk][tx * 8];
            *(float4*)&rb[4] = *(const float4*)&Bs[kk][tx * 8 + 4];
            #pragma unroll
            for (int i = 0; i < 8; i++)
                #pragma unroll
                for (int j = 0; j < 8; j++)
                    acc[i][j] = fmaf(ra[i], rb[j], acc[i][j]);
        }
    }

    #pragma unroll
    for (int i = 0; i < 8; i++) {
        int m = m0 + ty * 8 + i;
        float* pp = Dst + m * CC + ncol0 + tx * 8;
        float vals[8];
        #pragma unroll
        for (int j = 0; j < 8; j++) {
            float vv = acc[i][j];
            vals[j] = sig ? (1.0f / (1.0f + __expf(-vv))) : vv;
        }
        *(float4*)&pp[0] = *(float4*)&vals[0];
        *(float4*)&pp[4] = *(float4*)&vals[4];
    }
}

// ---------------- scan phase 1: chunk aggregates + local bwd states ----------
// grid = BB*NCH blocks, 256 threads (= c)
template<int JM>
__global__ __launch_bounds__(256) void scan_p1(const float* __restrict__ sd, int j)
{
    int c  = threadIdx.x;
    int b  = blockIdx.x >> 5;
    int ch = blockIdx.x & 31;
    float wneg = -__expf(sd[j * CC + c] * (1.0f / 4096.0f));
    int base = b * TT * CC + c;
    int s0 = ch * CLEN;

    // forward aggregate over [s0, s0+CLEN), "end" anchored at s0+CLEN
    float a = 0.0f, bb = 0.0f, p = -1e38f;
    #pragma unroll 4
    for (int i = 0; i < CLEN; i++) {
        int s = s0 + i;
        int t = seqmap<JM>(s);
        float kt = g_k[base + t * CC];
        float vt = g_v[base + t * CC];
        float q = fmaxf(p + wneg, kt);
        float e1 = __expf(p + wneg - q);
        float e2 = __expf(kt - q);
        a = e1 * a + e2 * vt; bb = e1 * bb + e2; p = q;
    }
    int ai = (b * NCH + ch) * CC + c;
    g_fA[ai] = a; g_fB[ai] = bb; g_fP[ai] = p;

    // backward: emit pre-update carry at each s (local suffix over (s, s1),
    // anchored s+1), final carry = chunk aggregate anchored at s0
    a = 0.0f; bb = 0.0f; p = -1e38f;
    #pragma unroll 4
    for (int i = CLEN - 1; i >= 0; i--) {
        int s = s0 + i;
        int t = seqmap<JM>(s);
        float kt = g_k[base + t * CC];
        float vt = g_v[base + t * CC];
        int si = base + s * CC;
        g_bA[si] = a; g_bB[si] = bb; g_bP[si] = p;
        float q = fmaxf(p + wneg, kt);
        float e1 = __expf(p + wneg - q);
        float e2 = __expf(kt - q);
        a = e1 * a + e2 * vt; bb = e1 * bb + e2; p = q;
    }
    g_bAg[ai] = a; g_bBg[ai] = bb; g_bPg[ai] = p;
}

// ---------------- scan phase 2: cross-chunk prefixes / suffixes --------------
// grid = 16 blocks x 256 threads = one thread per (b,c)
__global__ __launch_bounds__(256) void scan_p2(const float* __restrict__ sd, int j)
{
    int idx = blockIdx.x * 256 + threadIdx.x;
    int b = idx >> 8;
    int c = idx & 255;
    float wneg = -__expf(sd[j * CC + c] * (1.0f / 4096.0f));
    float dec = (float)CLEN * wneg;

    // fwd exclusive chunk prefixes (carry state at chunk start)
    float a = 0.0f, bb = 0.0f, p = -1e38f;
    for (int ch = 0; ch < NCH; ch++) {
        int ai = (b * NCH + ch) * CC + c;
        g_pA[ai] = a; g_pB[ai] = bb; g_pP[ai] = p;
        float Aag = g_fA[ai], Bag = g_fB[ai], Pag = g_fP[ai];
        float q = fmaxf(p + dec, Pag);
        float e1 = __expf(p + dec - q), e2 = __expf(Pag - q);
        a = e1 * a + e2 * Aag; bb = e1 * bb + e2 * Bag; p = q;
    }
    // bwd exclusive chunk suffixes (anchored at chunk end)
    a = 0.0f; bb = 0.0f; p = -1e38f;
    for (int ch = NCH - 1; ch >= 0; ch--) {
        int ai = (b * NCH + ch) * CC + c;
        g_sA[ai] = a; g_sB[ai] = bb; g_sP[ai] = p;
        float Aag = g_bAg[ai], Bag = g_bBg[ai], Pag = g_bPg[ai];
        float q = fmaxf(Pag, p + dec);
        float e1 = __expf(Pag - q), e2 = __expf(p + dec - q);
        a = e1 * Aag + e2 * a; bb = e1 * Bag + e2 * bb; p = q;
    }
}

// ---------------- scan phase 3: fwd scan + 4-way combine, write v in place ---
template<int JM>
__global__ __launch_bounds__(256) void scan_p3(
    const float* __restrict__ sd, const float* __restrict__ sf, int j)
{
    int c  = threadIdx.x;
    int b  = blockIdx.x >> 5;
    int ch = blockIdx.x & 31;
    float wneg = -__expf(sd[j * CC + c] * (1.0f / 4096.0f));
    float u = sf[j * CC + c] * (1.0f / 4096.0f);
    int base = b * TT * CC + c;
    int ai = (b * NCH + ch) * CC + c;

    float af = g_pA[ai], bf = g_pB[ai], pf = g_pP[ai];   // fwd carry seeded by prefix
    float Asf = g_sA[ai], Bsf = g_sB[ai], Psf = g_sP[ai]; // bwd suffix (anchored chunk end)
    int s0 = ch * CLEN;

    #pragma unroll 2
    for (int i = 0; i < CLEN; i++) {
        int s = s0 + i;
        int t = seqmap<JM>(s);
        int ti = base + t * CC;
        int si = base + s * CC;
        float kt = g_k[ti];
        float vt = g_v[ti];
        float al = g_bA[si], bl = g_bB[si], pl = g_bP[si];

        // suffix contribution shifted to anchor s+1
        float dcy = Psf + (float)(CLEN - 1 - i) * wneg;
        float ps = u + kt;
        float q = fmaxf(fmaxf(pf, pl), fmaxf(dcy, ps));
        float ef = __expf(pf - q);
        float el = __expf(pl - q);
        float ed = __expf(dcy - q);
        float es = __expf(ps - q);
        float num = ef * af + el * al + ed * Asf + es * vt;
        float den = ef * bf + el * bl + ed * Bsf + es;
        g_v[ti] = num / den;

        // forward carry update (uses original vt)
        float qn = fmaxf(pf + wneg, kt);
        float e1 = __expf(pf + wneg - qn);
        float e2 = __expf(kt - qn);
        af = e1 * af + e2 * vt; bf = e1 * bf + e2; pf = qn;
    }
}

// ---------------- launcher ---------------------------------------------------
extern "C" void kernel_launch(void* const* d_in, const int* in_sizes, int n_in,
                              void* d_out, int out_size)
{
    const float *x = nullptr, *alpha = nullptr, *w1 = nullptr, *w3 = nullptr, *w5 = nullptr;
    const float* Wm[4] = {nullptr, nullptr, nullptr, nullptr}; // Wk, Wv, Wr, Wo (in order)
    const float* S2[2] = {nullptr, nullptr};                   // spatial_decay, spatial_first
    int nW = 0, nS = 0;
    for (int i = 0; i < n_in; i++) {
        int sz = in_sizes[i];
        const float* p = (const float*)d_in[i];
        if      (sz == NELEM) x = p;
        else if (sz == 4)     alpha = p;
        else if (sz == 256)   w1 = p;
        else if (sz == 2304)  w3 = p;
        else if (sz == 6400)  w5 = p;
        else if (sz == 65536) { if (nW < 4) Wm[nW++] = p; }
        else if (sz == 512)   { if (nS < 2) S2[nS++] = p; }
        // size-1 scalars (height/width) ignored — dims are compile-time
    }

    // 1. omni_shift -> g_xs
    omni_kernel<<<BB * WWD, 256>>>(x, alpha, w1, w3, w5);

    // 2. fused k/v/sigmoid(r) GEMMs
    gemm_kernel<0><<<dim3(6, 512), 256>>>(Wm[0], Wm[1], Wm[2], nullptr);

    // 3. rec 0: H-scan (row-major)
    scan_p1<0><<<BB * NCH, 256>>>(S2[0], 0);
    scan_p2<<<16, 256>>>(S2[0], 0);
    scan_p3<0><<<BB * NCH, 256>>>(S2[0], S2[1], 0);

    // 4. rec 1: W-scan (column-major)
    scan_p1<1><<<BB * NCH, 256>>>(S2[0], 1);
    scan_p2<<<16, 256>>>(S2[0], 1);
    scan_p3<1><<<BB * NCH, 256>>>(S2[0], S2[1], 1);

    // 5. (sr * v) @ Wo -> d_out
    gemm_kernel<1><<<dim3(2, 512), 256>>>(Wm[3], nullptr, nullptr, (float*)d_out);
}